// round 1
// baseline (speedup 1.0000x reference)
#include <cuda_runtime.h>
#include <cuda_bf16.h>
#include <math_constants.h>

// ---------------------------------------------------------------------------
// SelfAttention: B=8, S=2048, D=1024, fp32
//   Q = x @ Wq^T + bq ; K = x @ Wk^T + bk ; V = x @ Wv^T + bv
//   S = (Q @ K^T) * D^-0.5 ; P = softmax_rows(S) ; O = P @ V
// Pipeline: 3x gemm_nt (projections, fused bias) -> gemm_nt batched (scores,
// fused scale) -> row softmax -> gemm_nn batched (P @ V) into d_out.
// ---------------------------------------------------------------------------

#define BATCH 8
#define SEQ   2048
#define DIM   1024

#define BM 128
#define BN 128
#define BK 8
#define TM 8
#define TN 8
#define NTHREADS 256

// Scratch (allocation-free rule: __device__ globals)
static __device__ float g_Q[(size_t)BATCH * SEQ * DIM];
static __device__ float g_K[(size_t)BATCH * SEQ * DIM];
static __device__ float g_V[(size_t)BATCH * SEQ * DIM];
static __device__ float g_S[(size_t)BATCH * SEQ * SEQ];

// ---------------------------------------------------------------------------
// C[M,N] = alpha * A[M,K] @ B[N,K]^T (+ bias[N])     (both operands K-major)
// Batched via blockIdx.z with element strides sA/sB/sC.
// ---------------------------------------------------------------------------
__global__ __launch_bounds__(NTHREADS, 2)
void gemm_nt(const float* __restrict__ A, const float* __restrict__ B,
             const float* __restrict__ bias, float* __restrict__ C,
             int M, int N, int K, float alpha,
             size_t sA, size_t sB, size_t sC)
{
    A += (size_t)blockIdx.z * sA;
    B += (size_t)blockIdx.z * sB;
    C += (size_t)blockIdx.z * sC;

    __shared__ float As[BK][BM];
    __shared__ float Bs[BK][BN];

    const int tid  = threadIdx.x;
    const int bm   = blockIdx.y * BM;
    const int bn   = blockIdx.x * BN;
    const int lrow = tid >> 1;          // 0..127
    const int lcol = (tid & 1) << 2;    // 0 or 4
    const int tx   = tid & 15;
    const int ty   = tid >> 4;

    const float* Aptr = A + (size_t)(bm + lrow) * K + lcol;
    const float* Bptr = B + (size_t)(bn + lrow) * K + lcol;

    float acc[TM][TN] = {};

    for (int k0 = 0; k0 < K; k0 += BK) {
        float4 a4 = *(const float4*)(Aptr + k0);
        float4 b4 = *(const float4*)(Bptr + k0);
        As[lcol + 0][lrow] = a4.x; As[lcol + 1][lrow] = a4.y;
        As[lcol + 2][lrow] = a4.z; As[lcol + 3][lrow] = a4.w;
        Bs[lcol + 0][lrow] = b4.x; Bs[lcol + 1][lrow] = b4.y;
        Bs[lcol + 2][lrow] = b4.z; Bs[lcol + 3][lrow] = b4.w;
        __syncthreads();

        #pragma unroll
        for (int kk = 0; kk < BK; ++kk) {
            float a[TM], b[TN];
            #pragma unroll
            for (int i = 0; i < TM; ++i) a[i] = As[kk][ty * TM + i];
            #pragma unroll
            for (int j = 0; j < TN; ++j) b[j] = Bs[kk][tx * TN + j];
            #pragma unroll
            for (int i = 0; i < TM; ++i)
                #pragma unroll
                for (int j = 0; j < TN; ++j)
                    acc[i][j] += a[i] * b[j];
        }
        __syncthreads();
    }

    #pragma unroll
    for (int i = 0; i < TM; ++i) {
        size_t row = (size_t)(bm + ty * TM + i);
        #pragma unroll
        for (int j = 0; j < TN; j += 4) {
            int col = bn + tx * TN + j;
            float4 v;
            v.x = alpha * acc[i][j + 0];
            v.y = alpha * acc[i][j + 1];
            v.z = alpha * acc[i][j + 2];
            v.w = alpha * acc[i][j + 3];
            if (bias) {
                v.x += bias[col + 0]; v.y += bias[col + 1];
                v.z += bias[col + 2]; v.w += bias[col + 3];
            }
            *(float4*)(C + row * N + col) = v;
        }
    }
}

// ---------------------------------------------------------------------------
// C[M,N] = A[M,K] @ B[K,N]          (A K-major, B N-major)  — for P @ V
// ---------------------------------------------------------------------------
__global__ __launch_bounds__(NTHREADS, 2)
void gemm_nn(const float* __restrict__ A, const float* __restrict__ B,
             float* __restrict__ C,
             int M, int N, int K,
             size_t sA, size_t sB, size_t sC)
{
    A += (size_t)blockIdx.z * sA;
    B += (size_t)blockIdx.z * sB;
    C += (size_t)blockIdx.z * sC;

    __shared__ float As[BK][BM];
    __shared__ float Bs[BK][BN];

    const int tid  = threadIdx.x;
    const int bm   = blockIdx.y * BM;
    const int bn   = blockIdx.x * BN;
    const int lrow = tid >> 1;
    const int lcol = (tid & 1) << 2;
    const int tx   = tid & 15;
    const int ty   = tid >> 4;

    // B tile loader: 8 rows x 128 cols; thread -> (tid/32, (tid%32)*4)
    const int bkr = tid >> 5;
    const int bnc = (tid & 31) << 2;

    const float* Aptr = A + (size_t)(bm + lrow) * K + lcol;
    const float* Bptr = B + (size_t)bkr * N + bn + bnc;

    float acc[TM][TN] = {};

    for (int k0 = 0; k0 < K; k0 += BK) {
        float4 a4 = *(const float4*)(Aptr + k0);
        float4 b4 = *(const float4*)(Bptr + (size_t)k0 * N);
        As[lcol + 0][lrow] = a4.x; As[lcol + 1][lrow] = a4.y;
        As[lcol + 2][lrow] = a4.z; As[lcol + 3][lrow] = a4.w;
        *(float4*)&Bs[bkr][bnc] = b4;
        __syncthreads();

        #pragma unroll
        for (int kk = 0; kk < BK; ++kk) {
            float a[TM], b[TN];
            #pragma unroll
            for (int i = 0; i < TM; ++i) a[i] = As[kk][ty * TM + i];
            #pragma unroll
            for (int j = 0; j < TN; ++j) b[j] = Bs[kk][tx * TN + j];
            #pragma unroll
            for (int i = 0; i < TM; ++i)
                #pragma unroll
                for (int j = 0; j < TN; ++j)
                    acc[i][j] += a[i] * b[j];
        }
        __syncthreads();
    }

    #pragma unroll
    for (int i = 0; i < TM; ++i) {
        size_t row = (size_t)(bm + ty * TM + i);
        #pragma unroll
        for (int j = 0; j < TN; j += 4) {
            int col = bn + tx * TN + j;
            float4 v;
            v.x = acc[i][j + 0]; v.y = acc[i][j + 1];
            v.z = acc[i][j + 2]; v.w = acc[i][j + 3];
            *(float4*)(C + row * N + col) = v;
        }
    }
}

// ---------------------------------------------------------------------------
// Row softmax over 2048 columns, in place. One block (256 thr) per row.
// ---------------------------------------------------------------------------
__global__ __launch_bounds__(256)
void softmax2048(float* __restrict__ S)
{
    float* row = S + (size_t)blockIdx.x * SEQ;
    const int t = threadIdx.x;

    float v[8];
    float m = -CUDART_INF_F;
    #pragma unroll
    for (int i = 0; i < 8; ++i) {
        v[i] = row[t + (i << 8)];
        m = fmaxf(m, v[i]);
    }
    #pragma unroll
    for (int o = 16; o; o >>= 1) m = fmaxf(m, __shfl_xor_sync(0xffffffffu, m, o));

    __shared__ float red_max[8];
    __shared__ float red_sum[8];
    if ((t & 31) == 0) red_max[t >> 5] = m;
    __syncthreads();
    float bmax = red_max[0];
    #pragma unroll
    for (int w = 1; w < 8; ++w) bmax = fmaxf(bmax, red_max[w]);

    float s = 0.f;
    #pragma unroll
    for (int i = 0; i < 8; ++i) {
        v[i] = __expf(v[i] - bmax);
        s += v[i];
    }
    #pragma unroll
    for (int o = 16; o; o >>= 1) s += __shfl_xor_sync(0xffffffffu, s, o);
    if ((t & 31) == 0) red_sum[t >> 5] = s;
    __syncthreads();
    float tot = 0.f;
    #pragma unroll
    for (int w = 0; w < 8; ++w) tot += red_sum[w];

    float inv = __frcp_rn(tot);
    #pragma unroll
    for (int i = 0; i < 8; ++i) row[t + (i << 8)] = v[i] * inv;
}

// ---------------------------------------------------------------------------

extern "C" void kernel_launch(void* const* d_in, const int* in_sizes, int n_in,
                              void* d_out, int out_size)
{
    const float* x  = (const float*)d_in[0];
    const float* Wq = (const float*)d_in[1];
    const float* bq = (const float*)d_in[2];
    const float* Wk = (const float*)d_in[3];
    const float* bk = (const float*)d_in[4];
    const float* Wv = (const float*)d_in[5];
    const float* bv = (const float*)d_in[6];
    float* out = (float*)d_out;

    float *Q, *K, *V, *S;
    cudaGetSymbolAddress((void**)&Q, g_Q);
    cudaGetSymbolAddress((void**)&K, g_K);
    cudaGetSymbolAddress((void**)&V, g_V);
    cudaGetSymbolAddress((void**)&S, g_S);

    const int M = BATCH * SEQ;           // 16384 flattened rows
    const float scale = 0.03125f;        // 1024^-0.5

    // --- QKV projections: [16384,1024] @ [1024,1024]^T + bias ---
    {
        dim3 grid(DIM / BN, M / BM, 1);
        gemm_nt<<<grid, NTHREADS>>>(x, Wq, bq, Q, M, DIM, DIM, 1.f, 0, 0, 0);
        gemm_nt<<<grid, NTHREADS>>>(x, Wk, bk, K, M, DIM, DIM, 1.f, 0, 0, 0);
        gemm_nt<<<grid, NTHREADS>>>(x, Wv, bv, V, M, DIM, DIM, 1.f, 0, 0, 0);
    }

    // --- scores: per batch  S = scale * Q @ K^T   [2048,2048] ---
    {
        dim3 grid(SEQ / BN, SEQ / BM, BATCH);
        gemm_nt<<<grid, NTHREADS>>>(Q, K, nullptr, S, SEQ, SEQ, DIM, scale,
                                    (size_t)SEQ * DIM, (size_t)SEQ * DIM,
                                    (size_t)SEQ * SEQ);
    }

    // --- softmax rows (in place) ---
    softmax2048<<<BATCH * SEQ, 256>>>(S);

    // --- output: per batch  O = P @ V   [2048,1024] ---
    {
        dim3 grid(DIM / BN, SEQ / BM, BATCH);
        gemm_nn<<<grid, NTHREADS>>>(S, V, out, SEQ, DIM, SEQ,
                                    (size_t)SEQ * SEQ, (size_t)SEQ * DIM,
                                    (size_t)SEQ * DIM);
    }
}

// round 2
// speedup vs baseline: 1.5705x; 1.5705x over previous
#include <cuda_runtime.h>
#include <cuda_bf16.h>
#include <math_constants.h>

// ---------------------------------------------------------------------------
// SelfAttention B=8, S=2048, D=1024 fp32 — split-bf16 tensor-core pipeline.
//   Q = x Wq^T + bq ; K = x Wk^T + bk ; Vt = Wv x^T + bv (row bias)
//   S = scale * Q K^T ; P = softmax(S) ; O = P Vt^T   (PV uses NT form via Vt)
// All GEMMs: one NT kernel, A[m][k] & B[n][k] both K-contiguous.
// fp32 operands split into bf16 hi/lo; acc = Ah*Bh + Ah*Bl + Al*Bh (fp32 acc).
// ---------------------------------------------------------------------------

#define BATCH 8
#define SEQ   2048
#define DIM   1024

#define BM 128
#define BN 128
#define BKF 16          // k floats per stage
#define KPAD 24         // smem row pitch in halves (conflict-free: 48B rows)
#define NTHREADS 256

static __device__ float g_Q[(size_t)BATCH * SEQ * DIM];
static __device__ float g_K[(size_t)BATCH * SEQ * DIM];
static __device__ float g_Vt[(size_t)DIM * BATCH * SEQ];   // [1024][16384]
static __device__ float g_S[(size_t)BATCH * SEQ * SEQ];

// mma.sync m16n8k16 bf16 -> f32
__device__ __forceinline__ void mma16816(float c[4], const unsigned a[4], const unsigned b[2]) {
    asm volatile(
        "mma.sync.aligned.m16n8k16.row.col.f32.bf16.bf16.f32 "
        "{%0,%1,%2,%3}, {%4,%5,%6,%7}, {%8,%9}, {%0,%1,%2,%3};\n"
        : "+f"(c[0]), "+f"(c[1]), "+f"(c[2]), "+f"(c[3])
        : "r"(a[0]), "r"(a[1]), "r"(a[2]), "r"(a[3]), "r"(b[0]), "r"(b[1]));
}

__device__ __forceinline__ void cvt8(__nv_bfloat16* hi, __nv_bfloat16* lo,
                                     float4 x, float4 y) {
    float f[8] = {x.x, x.y, x.z, x.w, y.x, y.y, y.z, y.w};
    #pragma unroll
    for (int u = 0; u < 8; ++u) {
        __nv_bfloat16 h = __float2bfloat16(f[u]);
        hi[u] = h;
        lo[u] = __float2bfloat16(f[u] - __bfloat162float(h));
    }
}

// C[M,N] = alpha * A[M,K] @ B[N,K]^T (+biasCol[n]) (+biasRow[m])
// lda/ldb/ldc element strides; batch via blockIdx.z strides sA/sB/sC.
__global__ __launch_bounds__(NTHREADS, 1)
void gemm_bf16x3(const float* __restrict__ A, const float* __restrict__ B,
                 const float* __restrict__ biasCol, const float* __restrict__ biasRow,
                 float* __restrict__ C,
                 int M, int N, int K, int lda, int ldb, int ldc, float alpha,
                 size_t sA, size_t sB, size_t sC)
{
    A += (size_t)blockIdx.z * sA;
    B += (size_t)blockIdx.z * sB;
    C += (size_t)blockIdx.z * sC;

    // [stage][Ah,Al,Bh,Bl][row][k]  = 49152 bytes exactly
    __shared__ __nv_bfloat16 sm[2][4][BM][KPAD];

    const int tid  = threadIdx.x;
    const int lane = tid & 31;
    const int warp = tid >> 5;
    const int g    = lane >> 2;        // 0..7
    const int tg   = lane & 3;         // 0..3
    const int wm   = warp >> 2;        // 0..1  -> 64-row slab
    const int wn   = warp & 3;         // 0..3  -> 32-col slab
    const int m0   = wm * 64;
    const int n0   = wn * 32;

    const int bm = blockIdx.y * BM;
    const int bn = blockIdx.x * BN;

    // loaders: thread -> (row = tid/2, k-quarter = (tid&1)*8)
    const int lrow = tid >> 1;
    const int lkq  = (tid & 1) << 3;
    const float* Ap = A + (size_t)(bm + lrow) * lda + lkq;
    const float* Bp = B + (size_t)(bn + lrow) * ldb + lkq;

    float acc[4][4][4] = {};

    float4 pa0, pa1, pb0, pb1;

    // first tile
    pa0 = *(const float4*)(Ap + 0);
    pa1 = *(const float4*)(Ap + 4);
    pb0 = *(const float4*)(Bp + 0);
    pb1 = *(const float4*)(Bp + 4);
    cvt8(&sm[0][0][lrow][lkq], &sm[0][1][lrow][lkq], pa0, pa1);
    cvt8(&sm[0][2][lrow][lkq], &sm[0][3][lrow][lkq], pb0, pb1);
    __syncthreads();

    const int nk = K / BKF;
    for (int kt = 0; kt < nk; ++kt) {
        const int cur = kt & 1;
        const int nxt = cur ^ 1;

        if (kt + 1 < nk) {
            const float* Ap2 = Ap + (size_t)(kt + 1) * BKF;
            const float* Bp2 = Bp + (size_t)(kt + 1) * BKF;
            pa0 = *(const float4*)(Ap2 + 0);
            pa1 = *(const float4*)(Ap2 + 4);
            pb0 = *(const float4*)(Bp2 + 0);
            pb1 = *(const float4*)(Bp2 + 4);
        }

        // ---- fragment loads (half2, conflict-free) ----
        unsigned Ah[4][4], Al[4][4], Bh[4][2], Bl[4][2];
        #pragma unroll
        for (int i = 0; i < 4; ++i) {
            const int r = m0 + i * 16 + g;
            Ah[i][0] = *(const unsigned*)&sm[cur][0][r    ][tg * 2    ];
            Ah[i][1] = *(const unsigned*)&sm[cur][0][r + 8][tg * 2    ];
            Ah[i][2] = *(const unsigned*)&sm[cur][0][r    ][tg * 2 + 8];
            Ah[i][3] = *(const unsigned*)&sm[cur][0][r + 8][tg * 2 + 8];
            Al[i][0] = *(const unsigned*)&sm[cur][1][r    ][tg * 2    ];
            Al[i][1] = *(const unsigned*)&sm[cur][1][r + 8][tg * 2    ];
            Al[i][2] = *(const unsigned*)&sm[cur][1][r    ][tg * 2 + 8];
            Al[i][3] = *(const unsigned*)&sm[cur][1][r + 8][tg * 2 + 8];
        }
        #pragma unroll
        for (int j = 0; j < 4; ++j) {
            const int n = n0 + j * 8 + g;
            Bh[j][0] = *(const unsigned*)&sm[cur][2][n][tg * 2    ];
            Bh[j][1] = *(const unsigned*)&sm[cur][2][n][tg * 2 + 8];
            Bl[j][0] = *(const unsigned*)&sm[cur][3][n][tg * 2    ];
            Bl[j][1] = *(const unsigned*)&sm[cur][3][n][tg * 2 + 8];
        }

        // ---- 3-term split MMAs ----
        #pragma unroll
        for (int i = 0; i < 4; ++i)
            #pragma unroll
            for (int j = 0; j < 4; ++j) {
                mma16816(acc[i][j], Ah[i], Bh[j]);
                mma16816(acc[i][j], Ah[i], Bl[j]);
                mma16816(acc[i][j], Al[i], Bh[j]);
            }

        if (kt + 1 < nk) {
            cvt8(&sm[nxt][0][lrow][lkq], &sm[nxt][1][lrow][lkq], pa0, pa1);
            cvt8(&sm[nxt][2][lrow][lkq], &sm[nxt][3][lrow][lkq], pb0, pb1);
        }
        __syncthreads();
    }

    // ---- epilogue ----
    #pragma unroll
    for (int i = 0; i < 4; ++i) {
        const int row0 = bm + m0 + i * 16 + g;
        #pragma unroll
        for (int j = 0; j < 4; ++j) {
            const int col = bn + n0 + j * 8 + tg * 2;
            float bc0 = 0.f, bc1 = 0.f;
            if (biasCol) { bc0 = biasCol[col]; bc1 = biasCol[col + 1]; }
            float br0 = 0.f, br1 = 0.f;
            if (biasRow) { br0 = biasRow[row0]; br1 = biasRow[row0 + 8]; }
            float2 v0, v1;
            v0.x = alpha * acc[i][j][0] + bc0 + br0;
            v0.y = alpha * acc[i][j][1] + bc1 + br0;
            v1.x = alpha * acc[i][j][2] + bc0 + br1;
            v1.y = alpha * acc[i][j][3] + bc1 + br1;
            *(float2*)(C + (size_t)row0 * ldc + col)       = v0;
            *(float2*)(C + (size_t)(row0 + 8) * ldc + col) = v1;
        }
    }
}

// ---------------------------------------------------------------------------
// Row softmax over 2048 cols, in place. One 256-thread block per row.
// ---------------------------------------------------------------------------
__global__ __launch_bounds__(256)
void softmax2048(float* __restrict__ S)
{
    float* row = S + (size_t)blockIdx.x * SEQ;
    const int t = threadIdx.x;

    float v[8];
    float m = -CUDART_INF_F;
    #pragma unroll
    for (int i = 0; i < 8; ++i) {
        v[i] = row[t + (i << 8)];
        m = fmaxf(m, v[i]);
    }
    #pragma unroll
    for (int o = 16; o; o >>= 1) m = fmaxf(m, __shfl_xor_sync(0xffffffffu, m, o));

    __shared__ float red_max[8];
    __shared__ float red_sum[8];
    if ((t & 31) == 0) red_max[t >> 5] = m;
    __syncthreads();
    float bmax = red_max[0];
    #pragma unroll
    for (int w = 1; w < 8; ++w) bmax = fmaxf(bmax, red_max[w]);

    float s = 0.f;
    #pragma unroll
    for (int i = 0; i < 8; ++i) {
        v[i] = __expf(v[i] - bmax);
        s += v[i];
    }
    #pragma unroll
    for (int o = 16; o; o >>= 1) s += __shfl_xor_sync(0xffffffffu, s, o);
    if ((t & 31) == 0) red_sum[t >> 5] = s;
    __syncthreads();
    float tot = 0.f;
    #pragma unroll
    for (int w = 0; w < 8; ++w) tot += red_sum[w];

    float inv = __frcp_rn(tot);
    #pragma unroll
    for (int i = 0; i < 8; ++i) row[t + (i << 8)] = v[i] * inv;
}

// ---------------------------------------------------------------------------

extern "C" void kernel_launch(void* const* d_in, const int* in_sizes, int n_in,
                              void* d_out, int out_size)
{
    const float* x  = (const float*)d_in[0];
    const float* Wq = (const float*)d_in[1];
    const float* bq = (const float*)d_in[2];
    const float* Wk = (const float*)d_in[3];
    const float* bk = (const float*)d_in[4];
    const float* Wv = (const float*)d_in[5];
    const float* bv = (const float*)d_in[6];
    float* out = (float*)d_out;

    float *Q, *K, *Vt, *S;
    cudaGetSymbolAddress((void**)&Q,  g_Q);
    cudaGetSymbolAddress((void**)&K,  g_K);
    cudaGetSymbolAddress((void**)&Vt, g_Vt);
    cudaGetSymbolAddress((void**)&S,  g_S);

    const int M = BATCH * SEQ;            // 16384
    const float scale = 0.03125f;         // 1024^-0.5

    // Q, K projections: [16384,1024] = x @ W^T + b
    {
        dim3 grid(DIM / BN, M / BM, 1);
        gemm_bf16x3<<<grid, NTHREADS>>>(x, Wq, bq, nullptr, Q,
                                        M, DIM, DIM, DIM, DIM, DIM, 1.f, 0, 0, 0);
        gemm_bf16x3<<<grid, NTHREADS>>>(x, Wk, bk, nullptr, K,
                                        M, DIM, DIM, DIM, DIM, DIM, 1.f, 0, 0, 0);
    }

    // Vt = Wv @ x^T + bv (row bias): [1024, 16384]; B operand = x (N-major already)
    {
        dim3 grid(M / BN, DIM / BM, 1);
        gemm_bf16x3<<<grid, NTHREADS>>>(Wv, x, nullptr, bv, Vt,
                                        DIM, M, DIM, DIM, DIM, M, 1.f, 0, 0, 0);
    }

    // scores: per batch  S = scale * Q @ K^T   [2048,2048]
    {
        dim3 grid(SEQ / BN, SEQ / BM, BATCH);
        gemm_bf16x3<<<grid, NTHREADS>>>(Q, K, nullptr, nullptr, S,
                                        SEQ, SEQ, DIM, DIM, DIM, SEQ, scale,
                                        (size_t)SEQ * DIM, (size_t)SEQ * DIM,
                                        (size_t)SEQ * SEQ);
    }

    // softmax rows
    softmax2048<<<BATCH * SEQ, 256>>>(S);

    // O = P @ V = P @ (Vt slice)^T : NT gemm with B = Vt + b*2048, ldb = 16384
    {
        dim3 grid(DIM / BN, SEQ / BM, BATCH);
        gemm_bf16x3<<<grid, NTHREADS>>>(S, Vt, nullptr, nullptr, out,
                                        SEQ, DIM, SEQ, SEQ, M, DIM, 1.f,
                                        (size_t)SEQ * SEQ, (size_t)SEQ, (size_t)SEQ * DIM);
    }
}

// round 4
// speedup vs baseline: 2.1067x; 1.3414x over previous
#include <cuda_runtime.h>
#include <cuda_bf16.h>
#include <math_constants.h>
#include <cstdint>

// ---------------------------------------------------------------------------
// SelfAttention B=8, S=2048, D=1024 fp32 — split-bf16 mma.sync pipeline v2.
//   f = hi + lo (bf16);  A@B ≈ AhBh + AhBl + AlBh  (fp32 accum in registers)
//   cp.async 3-stage global->smem, ldmatrix.x4 fragment loads (80B pitch),
//   pre-split operands (bf16 hi/lo in gmem), epilogues emit bf16 hi/lo.
// Stages: split(x,W) -> Q,K (hi/lo) -> Vt (hi/lo, transposed) ->
//         S=scale*Q@K^T (fp32) -> softmax -> P(hi/lo) -> O = P@Vt^T (fp32)
// ---------------------------------------------------------------------------

#define BATCH 8
#define SEQ   2048
#define DIM   1024
#define MTOT  (BATCH*SEQ)

#define NTH    256
#define BKH    32                    // bf16 k per mainloop tile
#define PITCH  80                    // smem row pitch bytes (64 data + 16 pad)
#define TILEB  (128*PITCH)           // 10240 B per matrix tile
#define STAGE  (4*TILEB)             // Ah,Al,Bh,Bl = 40960 B
#define NSTAGE 3
#define SM_REQ (NSTAGE*STAGE)        // 122880 B

// ---- device scratch ----
static __device__ __nv_bfloat16 g_xh[(size_t)MTOT*DIM], g_xl[(size_t)MTOT*DIM];
static __device__ __nv_bfloat16 g_Wqh[DIM*DIM], g_Wql[DIM*DIM];
static __device__ __nv_bfloat16 g_Wkh[DIM*DIM], g_Wkl[DIM*DIM];
static __device__ __nv_bfloat16 g_Wvh[DIM*DIM], g_Wvl[DIM*DIM];
static __device__ __nv_bfloat16 g_Qh[(size_t)MTOT*DIM], g_Ql[(size_t)MTOT*DIM];
static __device__ __nv_bfloat16 g_Kh[(size_t)MTOT*DIM], g_Kl[(size_t)MTOT*DIM];
static __device__ __nv_bfloat16 g_Vth[(size_t)DIM*MTOT], g_Vtl[(size_t)DIM*MTOT];
static __device__ float         g_S[(size_t)BATCH*SEQ*SEQ];
static __device__ __nv_bfloat16 g_Ph[(size_t)BATCH*SEQ*SEQ], g_Pl[(size_t)BATCH*SEQ*SEQ];

// ---- helpers ----
__device__ __forceinline__ uint32_t smem_u32(const void* p) {
    uint32_t a;
    asm("{ .reg .u64 t; cvta.to.shared.u64 t, %1; cvt.u32.u64 %0, t; }" : "=r"(a) : "l"(p));
    return a;
}
__device__ __forceinline__ void cp16(uint32_t d, const void* s) {
    asm volatile("cp.async.cg.shared.global [%0], [%1], 16;" :: "r"(d), "l"(s) : "memory");
}
__device__ __forceinline__ void mma16816(float c[4], const unsigned a[4], const unsigned b[2]) {
    asm volatile(
        "mma.sync.aligned.m16n8k16.row.col.f32.bf16.bf16.f32 "
        "{%0,%1,%2,%3}, {%4,%5,%6,%7}, {%8,%9}, {%0,%1,%2,%3};\n"
        : "+f"(c[0]), "+f"(c[1]), "+f"(c[2]), "+f"(c[3])
        : "r"(a[0]), "r"(a[1]), "r"(a[2]), "r"(a[3]), "r"(b[0]), "r"(b[1]));
}
__device__ __forceinline__ void ldsm4(unsigned r[4], uint32_t a) {
    asm volatile("ldmatrix.sync.aligned.m8n8.x4.shared.b16 {%0,%1,%2,%3}, [%4];"
                 : "=r"(r[0]), "=r"(r[1]), "=r"(r[2]), "=r"(r[3]) : "r"(a));
}

// ---------------------------------------------------------------------------
// NT GEMM: C = alpha * A @ B^T   A[m][k] hi/lo, B[n][k] hi/lo (K-contig bf16)
// outMode 0: fp32 C = alpha*acc;  outMode 1: bf16 hi/lo (+biasCol/+biasRow)
// ---------------------------------------------------------------------------
__global__ __launch_bounds__(NTH, 1)
void gemm_hl(const __nv_bfloat16* __restrict__ Ah, const __nv_bfloat16* __restrict__ Al,
             const __nv_bfloat16* __restrict__ Bh, const __nv_bfloat16* __restrict__ Bl,
             const float* __restrict__ biasCol, const float* __restrict__ biasRow,
             float* __restrict__ C, __nv_bfloat16* __restrict__ Ch, __nv_bfloat16* __restrict__ Cl,
             int K, int lda, int ldb, int ldc, float alpha,
             size_t sA, size_t sB, size_t sC, int outMode)
{
    extern __shared__ char dyn[];
    const size_t bz = blockIdx.z;
    Ah += bz * sA; Al += bz * sA;
    Bh += bz * sB; Bl += bz * sB;
    if (C)  C  += bz * sC;
    if (Ch) { Ch += bz * sC; Cl += bz * sC; }

    const int tid  = threadIdx.x;
    const int warp = tid >> 5;
    const int lane = tid & 31;
    const int bm = blockIdx.y * 128;
    const int bn = blockIdx.x * 128;
    const int m0 = (warp >> 2) * 64;     // warp tile 64 x 32
    const int n0 = (warp & 3) * 32;

    const uint32_t sbase = smem_u32(dyn);

    // ---- loader mapping: thread -> row (0..127), 32B chunk pair ----
    const int lrow = tid >> 1;
    const int lc16 = (tid & 1) * 2;          // c16 in {0,2}
    const __nv_bfloat16* gsrc[4] = {
        Ah + (size_t)(bm + lrow) * lda + lc16 * 8,
        Al + (size_t)(bm + lrow) * lda + lc16 * 8,
        Bh + (size_t)(bn + lrow) * ldb + lc16 * 8,
        Bl + (size_t)(bn + lrow) * ldb + lc16 * 8 };
    const uint32_t sdst0 = (uint32_t)(lrow * PITCH + lc16 * 16);

    const int nk = K / BKH;

    auto issue_stage = [&](int kt) {
        const uint32_t dst = sbase + (uint32_t)(kt % NSTAGE) * STAGE + sdst0;
        const size_t koff = (size_t)kt * BKH;
        #pragma unroll
        for (int p = 0; p < 4; ++p) {
            const __nv_bfloat16* s = gsrc[p] + koff;
            cp16(dst + p * TILEB,      s);
            cp16(dst + p * TILEB + 16, s + 8);
        }
    };

    // prologue: stages 0..NSTAGE-2
    issue_stage(0);
    asm volatile("cp.async.commit_group;" ::: "memory");
    issue_stage(1);
    asm volatile("cp.async.commit_group;" ::: "memory");

    // ldmatrix per-lane address components
    const uint32_t lrow16  = (uint32_t)(lane & 15);       // row within 16-block
    const uint32_t lkhalf  = (uint32_t)(lane >> 4) * 16;  // 16B col half

    float acc[4][4][4] = {};

    for (int kt = 0; kt < nk; ++kt) {
        asm volatile("cp.async.wait_group 1;" ::: "memory");
        __syncthreads();

        if (kt + NSTAGE - 1 < nk) issue_stage(kt + NSTAGE - 1);
        asm volatile("cp.async.commit_group;" ::: "memory");

        const uint32_t st = sbase + (uint32_t)(kt % NSTAGE) * STAGE;
        const uint32_t aA = st + (uint32_t)((m0 + lrow16) * PITCH) + lkhalf;
        const uint32_t aB = st + (uint32_t)((n0 + lrow16) * PITCH) + lkhalf;

        #pragma unroll
        for (int ks = 0; ks < 2; ++ks) {
            const uint32_t kb = (uint32_t)(ks * 32);
            unsigned Ahf[4][4], Alf[4][4], Bhf[4][2], Blf[4][2];
            #pragma unroll
            for (int i = 0; i < 4; ++i) {
                ldsm4(Ahf[i], aA + 0 * TILEB + (uint32_t)(i * 16 * PITCH) + kb);
                ldsm4(Alf[i], aA + 1 * TILEB + (uint32_t)(i * 16 * PITCH) + kb);
            }
            #pragma unroll
            for (int q = 0; q < 2; ++q) {
                unsigned t[4];
                ldsm4(t, aB + 2 * TILEB + (uint32_t)(q * 16 * PITCH) + kb);
                Bhf[2*q  ][0] = t[0]; Bhf[2*q  ][1] = t[2];
                Bhf[2*q+1][0] = t[1]; Bhf[2*q+1][1] = t[3];
                ldsm4(t, aB + 3 * TILEB + (uint32_t)(q * 16 * PITCH) + kb);
                Blf[2*q  ][0] = t[0]; Blf[2*q  ][1] = t[2];
                Blf[2*q+1][0] = t[1]; Blf[2*q+1][1] = t[3];
            }
            #pragma unroll
            for (int i = 0; i < 4; ++i)
                #pragma unroll
                for (int j = 0; j < 4; ++j) {
                    mma16816(acc[i][j], Ahf[i], Bhf[j]);
                    mma16816(acc[i][j], Ahf[i], Blf[j]);
                    mma16816(acc[i][j], Alf[i], Bhf[j]);
                }
        }
        __syncthreads();
    }

    // ---- epilogue ----
    const int g  = lane >> 2;
    const int tg = lane & 3;
    #pragma unroll
    for (int i = 0; i < 4; ++i) {
        const int row0 = bm + m0 + i * 16 + g;
        #pragma unroll
        for (int j = 0; j < 4; ++j) {
            const int col = bn + n0 + j * 8 + tg * 2;
            float v00 = alpha * acc[i][j][0];
            float v01 = alpha * acc[i][j][1];
            float v10 = alpha * acc[i][j][2];
            float v11 = alpha * acc[i][j][3];
            if (outMode == 0) {
                *(float2*)(C + (size_t)row0 * ldc + col)       = make_float2(v00, v01);
                *(float2*)(C + (size_t)(row0 + 8) * ldc + col) = make_float2(v10, v11);
            } else {
                if (biasCol) {
                    float b0 = biasCol[col], b1 = biasCol[col + 1];
                    v00 += b0; v01 += b1; v10 += b0; v11 += b1;
                }
                if (biasRow) {
                    v00 += biasRow[row0];     v01 += biasRow[row0];
                    v10 += biasRow[row0 + 8]; v11 += biasRow[row0 + 8];
                }
                __nv_bfloat16 h00 = __float2bfloat16(v00), h01 = __float2bfloat16(v01);
                __nv_bfloat16 h10 = __float2bfloat16(v10), h11 = __float2bfloat16(v11);
                *(__nv_bfloat162*)(Ch + (size_t)row0 * ldc + col) = __nv_bfloat162(h00, h01);
                *(__nv_bfloat162*)(Ch + (size_t)(row0 + 8) * ldc + col) = __nv_bfloat162(h10, h11);
                *(__nv_bfloat162*)(Cl + (size_t)row0 * ldc + col) = __nv_bfloat162(
                    __float2bfloat16(v00 - __bfloat162float(h00)),
                    __float2bfloat16(v01 - __bfloat162float(h01)));
                *(__nv_bfloat162*)(Cl + (size_t)(row0 + 8) * ldc + col) = __nv_bfloat162(
                    __float2bfloat16(v10 - __bfloat162float(h10)),
                    __float2bfloat16(v11 - __bfloat162float(h11)));
            }
        }
    }
}

// ---------------------------------------------------------------------------
// fp32 -> bf16 hi/lo split (elementwise)
// ---------------------------------------------------------------------------
__global__ __launch_bounds__(256)
void split_hl(const float* __restrict__ in, __nv_bfloat16* __restrict__ hi,
              __nv_bfloat16* __restrict__ lo, size_t n4)
{
    size_t i = (size_t)blockIdx.x * blockDim.x + threadIdx.x;
    size_t stride = (size_t)gridDim.x * blockDim.x;
    for (; i < n4; i += stride) {
        float4 v = ((const float4*)in)[i];
        __nv_bfloat16 h0 = __float2bfloat16(v.x), h1 = __float2bfloat16(v.y);
        __nv_bfloat16 h2 = __float2bfloat16(v.z), h3 = __float2bfloat16(v.w);
        ((__nv_bfloat162*)hi)[2 * i + 0] = __nv_bfloat162(h0, h1);
        ((__nv_bfloat162*)hi)[2 * i + 1] = __nv_bfloat162(h2, h3);
        ((__nv_bfloat162*)lo)[2 * i + 0] = __nv_bfloat162(
            __float2bfloat16(v.x - __bfloat162float(h0)),
            __float2bfloat16(v.y - __bfloat162float(h1)));
        ((__nv_bfloat162*)lo)[2 * i + 1] = __nv_bfloat162(
            __float2bfloat16(v.z - __bfloat162float(h2)),
            __float2bfloat16(v.w - __bfloat162float(h3)));
    }
}

// ---------------------------------------------------------------------------
// Row softmax over 2048 cols -> P hi/lo bf16. One 256-thread block per row.
// ---------------------------------------------------------------------------
__global__ __launch_bounds__(256)
void softmax_hl(const float* __restrict__ S, __nv_bfloat16* __restrict__ Ph,
                __nv_bfloat16* __restrict__ Pl)
{
    const float* row = S + (size_t)blockIdx.x * SEQ;
    const int t = threadIdx.x;

    float4 a = ((const float4*)row)[2 * t];
    float4 b = ((const float4*)row)[2 * t + 1];
    float v[8] = {a.x, a.y, a.z, a.w, b.x, b.y, b.z, b.w};

    float m = v[0];
    #pragma unroll
    for (int i = 1; i < 8; ++i) m = fmaxf(m, v[i]);
    #pragma unroll
    for (int o = 16; o; o >>= 1) m = fmaxf(m, __shfl_xor_sync(0xffffffffu, m, o));

    __shared__ float red[8];
    if ((t & 31) == 0) red[t >> 5] = m;
    __syncthreads();
    float bmax = red[0];
    #pragma unroll
    for (int w = 1; w < 8; ++w) bmax = fmaxf(bmax, red[w]);
    __syncthreads();

    float s = 0.f;
    #pragma unroll
    for (int i = 0; i < 8; ++i) { v[i] = __expf(v[i] - bmax); s += v[i]; }
    #pragma unroll
    for (int o = 16; o; o >>= 1) s += __shfl_xor_sync(0xffffffffu, s, o);
    if ((t & 31) == 0) red[t >> 5] = s;
    __syncthreads();
    float tot = 0.f;
    #pragma unroll
    for (int w = 0; w < 8; ++w) tot += red[w];
    float inv = __frcp_rn(tot);

    __nv_bfloat162* ph = (__nv_bfloat162*)(Ph + (size_t)blockIdx.x * SEQ) + 4 * t;
    __nv_bfloat162* pl = (__nv_bfloat162*)(Pl + (size_t)blockIdx.x * SEQ) + 4 * t;
    #pragma unroll
    for (int j = 0; j < 4; ++j) {
        float p0 = v[2 * j] * inv, p1 = v[2 * j + 1] * inv;
        __nv_bfloat16 h0 = __float2bfloat16(p0), h1 = __float2bfloat16(p1);
        ph[j] = __nv_bfloat162(h0, h1);
        pl[j] = __nv_bfloat162(__float2bfloat16(p0 - __bfloat162float(h0)),
                               __float2bfloat16(p1 - __bfloat162float(h1)));
    }
}

// ---------------------------------------------------------------------------

extern "C" void kernel_launch(void* const* d_in, const int* in_sizes, int n_in,
                              void* d_out, int out_size)
{
    const float* x  = (const float*)d_in[0];
    const float* Wq = (const float*)d_in[1];
    const float* bq = (const float*)d_in[2];
    const float* Wk = (const float*)d_in[3];
    const float* bk = (const float*)d_in[4];
    const float* Wv = (const float*)d_in[5];
    const float* bv = (const float*)d_in[6];
    float* out = (float*)d_out;

    __nv_bfloat16 *xh, *xl, *Wqh, *Wql, *Wkh, *Wkl, *Wvh, *Wvl;
    __nv_bfloat16 *Qh, *Ql, *Kh, *Kl, *Vth, *Vtl, *Ph, *Pl;
    float* S;
    cudaGetSymbolAddress((void**)&xh, g_xh);   cudaGetSymbolAddress((void**)&xl, g_xl);
    cudaGetSymbolAddress((void**)&Wqh, g_Wqh); cudaGetSymbolAddress((void**)&Wql, g_Wql);
    cudaGetSymbolAddress((void**)&Wkh, g_Wkh); cudaGetSymbolAddress((void**)&Wkl, g_Wkl);
    cudaGetSymbolAddress((void**)&Wvh, g_Wvh); cudaGetSymbolAddress((void**)&Wvl, g_Wvl);
    cudaGetSymbolAddress((void**)&Qh, g_Qh);   cudaGetSymbolAddress((void**)&Ql, g_Ql);
    cudaGetSymbolAddress((void**)&Kh, g_Kh);   cudaGetSymbolAddress((void**)&Kl, g_Kl);
    cudaGetSymbolAddress((void**)&Vth, g_Vth); cudaGetSymbolAddress((void**)&Vtl, g_Vtl);
    cudaGetSymbolAddress((void**)&Ph, g_Ph);   cudaGetSymbolAddress((void**)&Pl, g_Pl);
    cudaGetSymbolAddress((void**)&S, g_S);

    cudaFuncSetAttribute(gemm_hl, cudaFuncAttributeMaxDynamicSharedMemorySize, SM_REQ);

    const float scale = 0.03125f;   // 1024^-0.5

    // split inputs
    split_hl<<<1024, 256>>>(x,  xh,  xl,  (size_t)MTOT * DIM / 4);
    split_hl<<<256, 256>>>(Wq, Wqh, Wql, (size_t)DIM * DIM / 4);
    split_hl<<<256, 256>>>(Wk, Wkh, Wkl, (size_t)DIM * DIM / 4);
    split_hl<<<256, 256>>>(Wv, Wvh, Wvl, (size_t)DIM * DIM / 4);

    // Q = x Wq^T + bq ; K = x Wk^T + bk  -> bf16 hi/lo
    {
        dim3 grid(DIM / 128, MTOT / 128, 1);
        gemm_hl<<<grid, NTH, SM_REQ>>>(xh, xl, Wqh, Wql, bq, nullptr,
                                       nullptr, Qh, Ql,
                                       DIM, DIM, DIM, DIM, 1.f, 0, 0, 0, 1);
        gemm_hl<<<grid, NTH, SM_REQ>>>(xh, xl, Wkh, Wkl, bk, nullptr,
                                       nullptr, Kh, Kl,
                                       DIM, DIM, DIM, DIM, 1.f, 0, 0, 0, 1);
    }
    // Vt = Wv x^T + bv(row) : [1024, 16384] -> bf16 hi/lo
    {
        dim3 grid(MTOT / 128, DIM / 128, 1);
        gemm_hl<<<grid, NTH, SM_REQ>>>(Wvh, Wvl, xh, xl, nullptr, bv,
                                       nullptr, Vth, Vtl,
                                       DIM, DIM, DIM, MTOT, 1.f, 0, 0, 0, 1);
    }
    // S = scale * Q K^T per batch  (fp32)
    {
        dim3 grid(SEQ / 128, SEQ / 128, BATCH);
        gemm_hl<<<grid, NTH, SM_REQ>>>(Qh, Ql, Kh, Kl, nullptr, nullptr,
                                       S, nullptr, nullptr,
                                       DIM, DIM, DIM, SEQ, scale,
                                       (size_t)SEQ * DIM, (size_t)SEQ * DIM,
                                       (size_t)SEQ * SEQ, 0);
    }
    // softmax -> P hi/lo
    softmax_hl<<<BATCH * SEQ, 256>>>(S, Ph, Pl);

    // O = P @ Vt^T per batch (fp32 out); B batch offset = b*2048 cols of Vt
    {
        dim3 grid(DIM / 128, SEQ / 128, BATCH);
        gemm_hl<<<grid, NTH, SM_REQ>>>(Ph, Pl, Vth, Vtl, nullptr, nullptr,
                                       out, nullptr, nullptr,
                                       SEQ, SEQ, MTOT, DIM, 1.f,
                                       (size_t)SEQ * SEQ, (size_t)SEQ,
                                       (size_t)SEQ * DIM, 0);
    }
}